// round 1
// baseline (speedup 1.0000x reference)
#include <cuda_runtime.h>
#include <math_constants.h>

#define C_DIM 1024
#define C3    3072
#define NH    16
#define HD    64
#define B_SZ  2
#define T_SZ  2048
#define M_ROWS (B_SZ*T_SZ)

#define ATT_SCALE 0.5f   /* 1/sqrt(d//h) = 1/sqrt(4) per reference */
#define LOG2E 1.4426950408889634f

// Scratch (no device allocation allowed)
__device__ float g_qkv[(size_t)M_ROWS * C3];
__device__ float g_attn[(size_t)M_ROWS * C_DIM];

// ---------------------------------------------------------------------------
// Tiled SGEMM + bias: C[M,N] = A[M,K] @ B[K,N] + bias[N]
// 64x64 tile, BK=16, 256 threads, 4x4 register micro-tile per thread.
// Requires M%64==0, N%64==0, K%16==0 (true for all calls here).
// ---------------------------------------------------------------------------
__global__ void __launch_bounds__(256) sgemm_bias_kernel(
    const float* __restrict__ A, const float* __restrict__ B,
    const float* __restrict__ bias, float* __restrict__ C,
    int M, int N, int K)
{
    __shared__ float As[16][68];  // [k][m]
    __shared__ float Bs[16][68];  // [k][n]

    const int tid = threadIdx.x;
    const int ty = tid >> 4, tx = tid & 15;
    const int row0 = blockIdx.y * 64;
    const int col0 = blockIdx.x * 64;

    const int a_row = tid >> 2;          // 0..63
    const int a_k4  = (tid & 3) * 4;     // 0,4,8,12
    const int b_k   = tid >> 4;          // 0..15
    const int b_c4  = (tid & 15) * 4;    // 0..60

    float acc[4][4] = {};

    for (int k0 = 0; k0 < K; k0 += 16) {
        float4 av = *(const float4*)&A[(size_t)(row0 + a_row) * K + k0 + a_k4];
        As[a_k4 + 0][a_row] = av.x;
        As[a_k4 + 1][a_row] = av.y;
        As[a_k4 + 2][a_row] = av.z;
        As[a_k4 + 3][a_row] = av.w;
        *(float4*)&Bs[b_k][b_c4] =
            *(const float4*)&B[(size_t)(k0 + b_k) * N + col0 + b_c4];
        __syncthreads();

#pragma unroll
        for (int kk = 0; kk < 16; kk++) {
            float4 a4 = *(const float4*)&As[kk][ty * 4];
            float4 b4 = *(const float4*)&Bs[kk][tx * 4];
            float av_[4] = {a4.x, a4.y, a4.z, a4.w};
            float bv_[4] = {b4.x, b4.y, b4.z, b4.w};
#pragma unroll
            for (int u = 0; u < 4; u++)
#pragma unroll
                for (int v = 0; v < 4; v++)
                    acc[u][v] += av_[u] * bv_[v];
        }
        __syncthreads();
    }

#pragma unroll
    for (int u = 0; u < 4; u++) {
        int r = row0 + ty * 4 + u;
        int c = col0 + tx * 4;
        float4 bb = *(const float4*)&bias[c];
        float4 ov = make_float4(acc[u][0] + bb.x, acc[u][1] + bb.y,
                                acc[u][2] + bb.z, acc[u][3] + bb.w);
        *(float4*)&C[(size_t)r * N + c] = ov;
    }
}

// ---------------------------------------------------------------------------
// Flash attention, fp32. One block = 64 query rows of one (b,h).
// Q is pre-scaled by ATT_SCALE*log2(e) so softmax runs in exp2 domain.
// 256 threads, 4x4 micro-tiles (ty: 16 row groups, tx: 16 col groups).
// ---------------------------------------------------------------------------
extern __shared__ float fa_smem[];

__global__ void __launch_bounds__(256) flash_attn_kernel(
    const float* __restrict__ qkv, float* __restrict__ out)
{
    float* Qt = fa_smem;               // [d][i]  ld=68 (q pre-scaled)
    float* Kt = fa_smem + 64 * 68;     // [d][j]  ld=68
    float* Vs = fa_smem + 2 * 64 * 68; // [j][dd] ld=68
    float* Ps = fa_smem + 3 * 64 * 68; // [i][j]  ld=68

    const int tid = threadIdx.x;
    const int ty = tid >> 4, tx = tid & 15;
    const int qt = blockIdx.x;
    const int b  = blockIdx.y >> 4;
    const int h  = blockIdx.y & 15;

    const float* qb = qkv + (size_t)b * T_SZ * C3 + h * HD;
    const float* kb = qb + C_DIM;
    const float* vb = qb + 2 * C_DIM;

    // Load Q tile (scaled into log2 domain)
    {
        const int i_base = tid >> 6;   // 0..3
        const int d = tid & 63;
#pragma unroll
        for (int r = 0; r < 16; r++) {
            int i = r * 4 + i_base;
            Qt[d * 68 + i] = qb[(size_t)(qt * 64 + i) * C3 + d] * (ATT_SCALE * LOG2E);
        }
    }

    float m_[4], l_[4], o_[4][4];
#pragma unroll
    for (int u = 0; u < 4; u++) {
        m_[u] = -CUDART_INF_F;
        l_[u] = 0.f;
#pragma unroll
        for (int v = 0; v < 4; v++) o_[u][v] = 0.f;
    }

    for (int st = 0; st < T_SZ / 64; st++) {
        __syncthreads();  // prev iter done reading Kt/Vs/Ps; Qt visible (iter 0)
        {
            const int j_base = tid >> 6;
            const int d = tid & 63;
#pragma unroll
            for (int r = 0; r < 16; r++) {
                int j = r * 4 + j_base;
                Kt[d * 68 + j] = kb[(size_t)(st * 64 + j) * C3 + d];
                Vs[j * 68 + d] = vb[(size_t)(st * 64 + j) * C3 + d];
            }
        }
        __syncthreads();

        // S[i][j] = sum_d Qt[d][i] * Kt[d][j]   (already in log2 units)
        float s[4][4] = {};
#pragma unroll
        for (int d = 0; d < 64; d++) {
            float4 qa = *(const float4*)&Qt[d * 68 + ty * 4];
            float4 ka = *(const float4*)&Kt[d * 68 + tx * 4];
            float qv[4] = {qa.x, qa.y, qa.z, qa.w};
            float kv[4] = {ka.x, ka.y, ka.z, ka.w};
#pragma unroll
            for (int u = 0; u < 4; u++)
#pragma unroll
                for (int v = 0; v < 4; v++)
                    s[u][v] += qv[u] * kv[v];
        }

        // Online softmax (per q-row; row owned by 16 threads across tx)
#pragma unroll
        for (int u = 0; u < 4; u++) {
            float mt = fmaxf(fmaxf(s[u][0], s[u][1]), fmaxf(s[u][2], s[u][3]));
#pragma unroll
            for (int msk = 1; msk < 16; msk <<= 1)
                mt = fmaxf(mt, __shfl_xor_sync(0xffffffffu, mt, msk));
            float mn = fmaxf(m_[u], mt);
            float f = exp2f(m_[u] - mn);   // 0 on first tile (-inf - finite)
            float p0 = exp2f(s[u][0] - mn);
            float p1 = exp2f(s[u][1] - mn);
            float p2 = exp2f(s[u][2] - mn);
            float p3 = exp2f(s[u][3] - mn);
            float rs = p0 + p1 + p2 + p3;
#pragma unroll
            for (int msk = 1; msk < 16; msk <<= 1)
                rs += __shfl_xor_sync(0xffffffffu, rs, msk);
            l_[u] = l_[u] * f + rs;
            m_[u] = mn;
#pragma unroll
            for (int v = 0; v < 4; v++) o_[u][v] *= f;
            *(float4*)&Ps[(ty * 4 + u) * 68 + tx * 4] = make_float4(p0, p1, p2, p3);
        }
        __syncthreads();

        // O[i][dd] += sum_j Ps[i][j] * Vs[j][dd]
#pragma unroll 4
        for (int j = 0; j < 64; j++) {
            float4 vv = *(const float4*)&Vs[j * 68 + tx * 4];
            float vr[4] = {vv.x, vv.y, vv.z, vv.w};
            float pa[4];
#pragma unroll
            for (int u = 0; u < 4; u++) pa[u] = Ps[(ty * 4 + u) * 68 + j];
#pragma unroll
            for (int u = 0; u < 4; u++)
#pragma unroll
                for (int v = 0; v < 4; v++)
                    o_[u][v] += pa[u] * vr[v];
        }
    }

    // Normalize and write: out[(b*T + i)*C + h*64 + dd]
#pragma unroll
    for (int u = 0; u < 4; u++) {
        int i = qt * 64 + ty * 4 + u;
        float inv = 1.f / l_[u];
        float4 ov = make_float4(o_[u][0] * inv, o_[u][1] * inv,
                                o_[u][2] * inv, o_[u][3] * inv);
        *(float4*)&out[((size_t)b * T_SZ + i) * C_DIM + h * HD + tx * 4] = ov;
    }
}

// ---------------------------------------------------------------------------
extern "C" void kernel_launch(void* const* d_in, const int* in_sizes, int n_in,
                              void* d_out, int out_size)
{
    const float* x     = (const float*)d_in[0];
    const float* Wqkv  = (const float*)d_in[1];
    const float* bqkv  = (const float*)d_in[2];
    const float* Wproj = (const float*)d_in[3];
    const float* bproj = (const float*)d_in[4];
    float* out = (float*)d_out;

    float* qkv;  cudaGetSymbolAddress((void**)&qkv,  g_qkv);
    float* attn; cudaGetSymbolAddress((void**)&attn, g_attn);

    const int FA_SMEM = 4 * 64 * 68 * (int)sizeof(float);  // 69632 B
    cudaFuncSetAttribute(flash_attn_kernel,
                         cudaFuncAttributeMaxDynamicSharedMemorySize, FA_SMEM);

    dim3 blk(256);
    // 1) qkv = x @ Wqkv + bqkv        [4096 x 3072]
    sgemm_bias_kernel<<<dim3(C3 / 64, M_ROWS / 64), blk>>>(
        x, Wqkv, bqkv, qkv, M_ROWS, C3, C_DIM);
    // 2) attention                    [4096 x 1024]
    flash_attn_kernel<<<dim3(T_SZ / 64, B_SZ * NH), blk, FA_SMEM>>>(qkv, attn);
    // 3) out = attn @ Wproj + bproj   [4096 x 1024]
    sgemm_bias_kernel<<<dim3(C_DIM / 64, M_ROWS / 64), blk>>>(
        attn, Wproj, bproj, out, M_ROWS, C_DIM, C_DIM);
}

// round 2
// speedup vs baseline: 1.0271x; 1.0271x over previous
#include <cuda_runtime.h>
#include <math_constants.h>

#define C_DIM 1024
#define C3    3072
#define NH    16
#define HD    64
#define B_SZ  2
#define T_SZ  2048
#define M_ROWS (B_SZ*T_SZ)

#define ATT_SCALE 0.5f   /* 1/sqrt(d//h) = 1/sqrt(4) per reference */
#define LOG2E 1.4426950408889634f

typedef unsigned long long u64;

// Packed f32x2 helpers (sm_103a double-rate fp32)
__device__ __forceinline__ u64 pack2(float lo, float hi) {
    u64 r; asm("mov.b64 %0, {%1, %2};" : "=l"(r) : "f"(lo), "f"(hi)); return r;
}
__device__ __forceinline__ u64 dup2(float v) {
    u64 r; asm("mov.b64 %0, {%1, %1};" : "=l"(r) : "f"(v)); return r;
}
__device__ __forceinline__ void unpack2(u64 v, float& lo, float& hi) {
    asm("mov.b64 {%0, %1}, %2;" : "=f"(lo), "=f"(hi) : "l"(v));
}
__device__ __forceinline__ void fma2(u64& d, u64 a, u64 b) {
    asm("fma.rn.f32x2 %0, %1, %2, %3;" : "=l"(d) : "l"(a), "l"(b), "l"(d));
}
__device__ __forceinline__ u64 mul2(u64 a, u64 b) {
    u64 r; asm("mul.rn.f32x2 %0, %1, %2;" : "=l"(r) : "l"(a), "l"(b)); return r;
}
__device__ __forceinline__ float fast_exp2(float x) {
    float r; asm("ex2.approx.ftz.f32 %0, %1;" : "=f"(r) : "f"(x)); return r;
}

// Scratch (no device allocation allowed)
__device__ float g_qkv[(size_t)M_ROWS * C3];
__device__ float g_attn[(size_t)M_ROWS * C_DIM];

// ---------------------------------------------------------------------------
// SGEMM + bias, f32x2 inner product.
// 128x128 tile, BK=8, 256 threads, 8x8 micro-tile per thread.
// Requires M%128==0, N%128==0, K%8==0.
// ---------------------------------------------------------------------------
__global__ void __launch_bounds__(256) sgemm_bias_kernel(
    const float* __restrict__ A, const float* __restrict__ B,
    const float* __restrict__ bias, float* __restrict__ C,
    int M, int N, int K)
{
    __shared__ float As[8][128];  // [k][m]
    __shared__ float Bs[8][128];  // [k][n]

    const int tid = threadIdx.x;
    const int ty = tid >> 4, tx = tid & 15;
    const int row0 = blockIdx.y * 128;
    const int col0 = blockIdx.x * 128;

    const int a_row = tid >> 1;        // 0..127
    const int a_k4  = (tid & 1) * 4;   // 0,4
    const int b_k   = tid >> 5;        // 0..7
    const int b_c4  = (tid & 31) * 4;  // 0..124

    u64 acc[8][4];
#pragma unroll
    for (int u = 0; u < 8; u++)
#pragma unroll
        for (int v = 0; v < 4; v++) acc[u][v] = 0ull;

    for (int k0 = 0; k0 < K; k0 += 8) {
        float4 av = *(const float4*)&A[(size_t)(row0 + a_row) * K + k0 + a_k4];
        As[a_k4 + 0][a_row] = av.x;
        As[a_k4 + 1][a_row] = av.y;
        As[a_k4 + 2][a_row] = av.z;
        As[a_k4 + 3][a_row] = av.w;
        *(float4*)&Bs[b_k][b_c4] =
            *(const float4*)&B[(size_t)(k0 + b_k) * N + col0 + b_c4];
        __syncthreads();

#pragma unroll
        for (int kk = 0; kk < 8; kk++) {
            float4 a0 = *(const float4*)&As[kk][ty * 8];
            float4 a1 = *(const float4*)&As[kk][ty * 8 + 4];
            float4 b0 = *(const float4*)&Bs[kk][tx * 8];
            float4 b1 = *(const float4*)&Bs[kk][tx * 8 + 4];
            u64 bb[4] = {pack2(b0.x, b0.y), pack2(b0.z, b0.w),
                         pack2(b1.x, b1.y), pack2(b1.z, b1.w)};
            float aa[8] = {a0.x, a0.y, a0.z, a0.w, a1.x, a1.y, a1.z, a1.w};
#pragma unroll
            for (int u = 0; u < 8; u++) {
                u64 ad = dup2(aa[u]);
#pragma unroll
                for (int v = 0; v < 4; v++) fma2(acc[u][v], ad, bb[v]);
            }
        }
        __syncthreads();
    }

#pragma unroll
    for (int u = 0; u < 8; u++) {
        int r = row0 + ty * 8 + u;
        int c = col0 + tx * 8;
        float4 bb0 = *(const float4*)&bias[c];
        float4 bb1 = *(const float4*)&bias[c + 4];
        float c0, c1, c2, c3, c4, c5, c6, c7;
        unpack2(acc[u][0], c0, c1);
        unpack2(acc[u][1], c2, c3);
        unpack2(acc[u][2], c4, c5);
        unpack2(acc[u][3], c6, c7);
        *(float4*)&C[(size_t)r * N + c] =
            make_float4(c0 + bb0.x, c1 + bb0.y, c2 + bb0.z, c3 + bb0.w);
        *(float4*)&C[(size_t)r * N + c + 4] =
            make_float4(c4 + bb1.x, c5 + bb1.y, c6 + bb1.z, c7 + bb1.w);
    }
}

// ---------------------------------------------------------------------------
// Flash attention, fp32 with f32x2 inner products. One block = 64 query rows
// of one (b,h). Q pre-scaled by ATT_SCALE*log2(e); softmax in exp2 domain.
// 256 threads, 4x4 micro-tiles (pairs along the column dim).
// ---------------------------------------------------------------------------
extern __shared__ float fa_smem[];

__global__ void __launch_bounds__(256) flash_attn_kernel(
    const float* __restrict__ qkv, float* __restrict__ out)
{
    float* Qt = fa_smem;               // [d][i]  ld=68 (q pre-scaled)
    float* Kt = fa_smem + 64 * 68;     // [d][j]  ld=68
    float* Vs = fa_smem + 2 * 64 * 68; // [j][dd] ld=68
    float* Ps = fa_smem + 3 * 64 * 68; // [i][j]  ld=68

    const int tid = threadIdx.x;
    const int ty = tid >> 4, tx = tid & 15;
    const int qt = blockIdx.x;
    const int b  = blockIdx.y >> 4;
    const int h  = blockIdx.y & 15;

    const float* qb = qkv + (size_t)b * T_SZ * C3 + h * HD;
    const float* kb = qb + C_DIM;
    const float* vb = qb + 2 * C_DIM;

    // Load Q tile (scaled into log2 domain)
    {
        const int i_base = tid >> 6;   // 0..3
        const int d = tid & 63;
#pragma unroll
        for (int r = 0; r < 16; r++) {
            int i = r * 4 + i_base;
            Qt[d * 68 + i] = qb[(size_t)(qt * 64 + i) * C3 + d] * (ATT_SCALE * LOG2E);
        }
    }

    float m_[4], l_[4];
    u64 o2[4][2];
#pragma unroll
    for (int u = 0; u < 4; u++) {
        m_[u] = -CUDART_INF_F;
        l_[u] = 0.f;
        o2[u][0] = 0ull; o2[u][1] = 0ull;
    }

    for (int st = 0; st < T_SZ / 64; st++) {
        __syncthreads();  // prev iter done reading Kt/Vs/Ps; Qt visible (iter 0)
        {
            const int j_base = tid >> 6;
            const int d = tid & 63;
#pragma unroll
            for (int r = 0; r < 16; r++) {
                int j = r * 4 + j_base;
                Kt[d * 68 + j] = kb[(size_t)(st * 64 + j) * C3 + d];
                Vs[j * 68 + d] = vb[(size_t)(st * 64 + j) * C3 + d];
            }
        }
        __syncthreads();

        // S[i][j] = sum_d Qt[d][i] * Kt[d][j]  (log2 units), f32x2 pairs on j
        u64 s2[4][2] = {{0ull, 0ull}, {0ull, 0ull}, {0ull, 0ull}, {0ull, 0ull}};
#pragma unroll
        for (int d = 0; d < 64; d++) {
            float4 qa = *(const float4*)&Qt[d * 68 + ty * 4];
            float4 ka = *(const float4*)&Kt[d * 68 + tx * 4];
            u64 k01 = pack2(ka.x, ka.y);
            u64 k23 = pack2(ka.z, ka.w);
            float qv[4] = {qa.x, qa.y, qa.z, qa.w};
#pragma unroll
            for (int u = 0; u < 4; u++) {
                u64 qd = dup2(qv[u]);
                fma2(s2[u][0], qd, k01);
                fma2(s2[u][1], qd, k23);
            }
        }

        // Online softmax (per q-row; row owned by 16 threads across tx)
#pragma unroll
        for (int u = 0; u < 4; u++) {
            float s0, s1, s2v, s3;
            unpack2(s2[u][0], s0, s1);
            unpack2(s2[u][1], s2v, s3);
            float mt = fmaxf(fmaxf(s0, s1), fmaxf(s2v, s3));
#pragma unroll
            for (int msk = 1; msk < 16; msk <<= 1)
                mt = fmaxf(mt, __shfl_xor_sync(0xffffffffu, mt, msk));
            float mn = fmaxf(m_[u], mt);
            float f = fast_exp2(m_[u] - mn);   // 0 on first tile
            float p0 = fast_exp2(s0 - mn);
            float p1 = fast_exp2(s1 - mn);
            float p2 = fast_exp2(s2v - mn);
            float p3 = fast_exp2(s3 - mn);
            float rs = p0 + p1 + p2 + p3;
#pragma unroll
            for (int msk = 1; msk < 16; msk <<= 1)
                rs += __shfl_xor_sync(0xffffffffu, rs, msk);
            l_[u] = l_[u] * f + rs;
            m_[u] = mn;
            u64 fd = dup2(f);
            o2[u][0] = mul2(o2[u][0], fd);
            o2[u][1] = mul2(o2[u][1], fd);
            *(float4*)&Ps[(ty * 4 + u) * 68 + tx * 4] = make_float4(p0, p1, p2, p3);
        }
        __syncthreads();

        // O[i][dd] += sum_j Ps[i][j] * Vs[j][dd], pairs on dd
#pragma unroll 4
        for (int j = 0; j < 64; j++) {
            float4 vv = *(const float4*)&Vs[j * 68 + tx * 4];
            u64 v01 = pack2(vv.x, vv.y);
            u64 v23 = pack2(vv.z, vv.w);
#pragma unroll
            for (int u = 0; u < 4; u++) {
                u64 pd = dup2(Ps[(ty * 4 + u) * 68 + j]);
                fma2(o2[u][0], pd, v01);
                fma2(o2[u][1], pd, v23);
            }
        }
    }

    // Normalize and write: out[(b*T + i)*C + h*64 + dd]
#pragma unroll
    for (int u = 0; u < 4; u++) {
        int i = qt * 64 + ty * 4 + u;
        float inv = 1.f / l_[u];
        float o0, o1, o2v, o3;
        unpack2(o2[u][0], o0, o1);
        unpack2(o2[u][1], o2v, o3);
        *(float4*)&out[((size_t)b * T_SZ + i) * C_DIM + h * HD + tx * 4] =
            make_float4(o0 * inv, o1 * inv, o2v * inv, o3 * inv);
    }
}

// ---------------------------------------------------------------------------
extern "C" void kernel_launch(void* const* d_in, const int* in_sizes, int n_in,
                              void* d_out, int out_size)
{
    const float* x     = (const float*)d_in[0];
    const float* Wqkv  = (const float*)d_in[1];
    const float* bqkv  = (const float*)d_in[2];
    const float* Wproj = (const float*)d_in[3];
    const float* bproj = (const float*)d_in[4];
    float* out = (float*)d_out;

    float* qkv;  cudaGetSymbolAddress((void**)&qkv,  g_qkv);
    float* attn; cudaGetSymbolAddress((void**)&attn, g_attn);

    const int FA_SMEM = 4 * 64 * 68 * (int)sizeof(float);  // 69632 B
    cudaFuncSetAttribute(flash_attn_kernel,
                         cudaFuncAttributeMaxDynamicSharedMemorySize, FA_SMEM);

    dim3 blk(256);
    // 1) qkv = x @ Wqkv + bqkv        [4096 x 3072]
    sgemm_bias_kernel<<<dim3(C3 / 128, M_ROWS / 128), blk>>>(
        x, Wqkv, bqkv, qkv, M_ROWS, C3, C_DIM);
    // 2) attention                    [4096 x 1024]
    flash_attn_kernel<<<dim3(T_SZ / 64, B_SZ * NH), blk, FA_SMEM>>>(qkv, attn);
    // 3) out = attn @ Wproj + bproj   [4096 x 1024]
    sgemm_bias_kernel<<<dim3(C_DIM / 128, M_ROWS / 128), blk>>>(
        attn, Wproj, bproj, out, M_ROWS, C_DIM, C_DIM);
}

// round 4
// speedup vs baseline: 1.4310x; 1.3932x over previous
#include <cuda_runtime.h>
#include <cuda_bf16.h>
#include <math_constants.h>

#define C_DIM 1024
#define C3    3072
#define NH    16
#define HD    64
#define B_SZ  2
#define T_SZ  2048
#define M_ROWS (B_SZ*T_SZ)

#define ATT_SCALE 0.5f
#define LOG2E 1.4426950408889634f

typedef unsigned long long u64;
typedef unsigned int u32;

// ---------------- scratch (no device allocation allowed) -------------------
__device__ float g_qkv[(size_t)M_ROWS * C3];
__device__ float g_attn[(size_t)M_ROWS * C_DIM];
__device__ __nv_bfloat16 g_xh[(size_t)M_ROWS * C_DIM];
__device__ __nv_bfloat16 g_xl[(size_t)M_ROWS * C_DIM];
__device__ __nv_bfloat16 g_ah[(size_t)M_ROWS * C_DIM];
__device__ __nv_bfloat16 g_al[(size_t)M_ROWS * C_DIM];
__device__ __nv_bfloat16 g_wqh[(size_t)C3 * C_DIM];   // Wqkv^T hi  [N][K]
__device__ __nv_bfloat16 g_wql[(size_t)C3 * C_DIM];
__device__ __nv_bfloat16 g_wph[(size_t)C_DIM * C_DIM];
__device__ __nv_bfloat16 g_wpl[(size_t)C_DIM * C_DIM];

// ---------------- helpers ----------------------------------------------------
__device__ __forceinline__ u32 smem_u32(const void* p) {
    u32 a; asm("{ .reg .u64 t; cvta.to.shared.u64 t, %1; cvt.u32.u64 %0, t; }"
               : "=r"(a) : "l"(p));
    return a;
}
__device__ __forceinline__ void ldsm_x4(u32& r0, u32& r1, u32& r2, u32& r3, u32 a) {
    asm volatile("ldmatrix.sync.aligned.m8n8.x4.shared.b16 {%0,%1,%2,%3}, [%4];"
                 : "=r"(r0), "=r"(r1), "=r"(r2), "=r"(r3) : "r"(a));
}
__device__ __forceinline__ void mma16816(float* c, const u32* a, const u32* b) {
    asm volatile(
        "mma.sync.aligned.m16n8k16.row.col.f32.bf16.bf16.f32 "
        "{%0,%1,%2,%3},{%4,%5,%6,%7},{%8,%9},{%0,%1,%2,%3};"
        : "+f"(c[0]), "+f"(c[1]), "+f"(c[2]), "+f"(c[3])
        : "r"(a[0]), "r"(a[1]), "r"(a[2]), "r"(a[3]), "r"(b[0]), "r"(b[1]));
}
__device__ __forceinline__ float fast_exp2(float x) {
    float r; asm("ex2.approx.ftz.f32 %0, %1;" : "=f"(r) : "f"(x)); return r;
}
#define CP_ASYNC16(d, s) asm volatile("cp.async.cg.shared.global [%0], [%1], 16;" :: "r"(d), "l"(s))
#define CP_COMMIT()      asm volatile("cp.async.commit_group;" ::: "memory")
#define CP_WAIT1()       asm volatile("cp.async.wait_group 1;" ::: "memory")
#define CP_WAIT0()       asm volatile("cp.async.wait_group 0;" ::: "memory")

// ---------------- prep: fp32 -> bf16 hi/lo split ----------------------------
__global__ void split_kernel(const float* __restrict__ in,
                             __nv_bfloat16* __restrict__ hi,
                             __nv_bfloat16* __restrict__ lo, int n4)
{
    int i = blockIdx.x * blockDim.x + threadIdx.x;
    if (i >= n4) return;
    float4 v = ((const float4*)in)[i];
    __nv_bfloat16 h0 = __float2bfloat16(v.x), h1 = __float2bfloat16(v.y);
    __nv_bfloat16 h2 = __float2bfloat16(v.z), h3 = __float2bfloat16(v.w);
    __nv_bfloat16 l0 = __float2bfloat16(v.x - __bfloat162float(h0));
    __nv_bfloat16 l1 = __float2bfloat16(v.y - __bfloat162float(h1));
    __nv_bfloat16 l2 = __float2bfloat16(v.z - __bfloat162float(h2));
    __nv_bfloat16 l3 = __float2bfloat16(v.w - __bfloat162float(h3));
    ((ushort4*)hi)[i] = make_ushort4(__bfloat16_as_ushort(h0), __bfloat16_as_ushort(h1),
                                     __bfloat16_as_ushort(h2), __bfloat16_as_ushort(h3));
    ((ushort4*)lo)[i] = make_ushort4(__bfloat16_as_ushort(l0), __bfloat16_as_ushort(l1),
                                     __bfloat16_as_ushort(l2), __bfloat16_as_ushort(l3));
}

// ---------------- prep: W[K][N] -> W^T hi/lo [N][K] -------------------------
__global__ void transpose_split_kernel(const float* __restrict__ W,
                                       __nv_bfloat16* __restrict__ Wh,
                                       __nv_bfloat16* __restrict__ Wl,
                                       int K, int N)
{
    __shared__ float ts[32][33];
    int n0 = blockIdx.x * 32, k0 = blockIdx.y * 32;
    int tx = threadIdx.x, ty = threadIdx.y;  // 32 x 8
#pragma unroll
    for (int r = 0; r < 4; r++)
        ts[ty + 8 * r][tx] = W[(size_t)(k0 + ty + 8 * r) * N + n0 + tx];
    __syncthreads();
#pragma unroll
    for (int r = 0; r < 4; r++) {
        float v = ts[tx][ty + 8 * r];
        __nv_bfloat16 h = __float2bfloat16(v);
        __nv_bfloat16 l = __float2bfloat16(v - __bfloat162float(h));
        size_t o = (size_t)(n0 + ty + 8 * r) * K + k0 + tx;
        Wh[o] = h; Wl[o] = l;
    }
}

// ---------------- warp-MMA bf16x3 GEMM + bias -------------------------------
// C[M,N] = (Ah+Al)[M,K] @ (Bh+Bl)^T[N,K] + bias[N]   (Al*Bl dropped)
// 128x128 CTA tile, BK=32, 8 warps (2m x 4n), 2-stage cp.async pipeline.
#define RSTRIDE 80                 // padded smem row stride (bytes) for 64B rows
#define ARR_B   (128 * RSTRIDE)    // one 128x32 bf16 tile
#define STAGE_B (4 * ARR_B)        // Ah, Al, Bh, Bl
#define GSMEM   (2 * STAGE_B)      // 81920 B

extern __shared__ char sm_raw[];

__global__ void __launch_bounds__(256) gemm_mma_kernel(
    const __nv_bfloat16* __restrict__ Ah, const __nv_bfloat16* __restrict__ Al,
    const __nv_bfloat16* __restrict__ Bh, const __nv_bfloat16* __restrict__ Bl,
    const float* __restrict__ bias, float* __restrict__ C,
    int M, int N, int K)
{
    const int tid = threadIdx.x, lane = tid & 31, wid = tid >> 5;
    const int warp_m = wid & 1, warp_n = wid >> 1;
    const int m0 = blockIdx.y * 128, n0 = blockIdx.x * 128;

    const int grp = lane >> 3, lrow = lane & 7;
    const int a_row = (grp & 1) * 8 + lrow, a_kb = (grp >> 1) * 16;
    const int b_row = (grp >> 1) * 8 + lrow, b_kb = (grp & 1) * 16;

    const __nv_bfloat16* srcs[4] = {Ah, Al, Bh, Bl};
    const int r0s[4] = {m0, m0, n0, n0};

    float cf[4][4][4];
#pragma unroll
    for (int tm = 0; tm < 4; tm++)
#pragma unroll
        for (int tn = 0; tn < 4; tn++)
#pragma unroll
            for (int q = 0; q < 4; q++) cf[tm][tn][q] = 0.f;

#define G_LOAD(st, k0)                                                          \
    do {                                                                        \
        char* _b = sm_raw + (st) * STAGE_B;                                     \
        _Pragma("unroll")                                                       \
        for (int t = 0; t < 4; t++) {                                           \
            const __nv_bfloat16* _s = srcs[t] + (size_t)r0s[t] * K + (k0);      \
            _Pragma("unroll")                                                   \
            for (int j = 0; j < 2; j++) {                                       \
                int _i = tid + j * 256;                                         \
                int _r = _i >> 2, _c = _i & 3;                                  \
                u32 _d = smem_u32(_b + t * ARR_B + _r * RSTRIDE + _c * 16);     \
                CP_ASYNC16(_d, _s + (size_t)_r * K + _c * 8);                   \
            }                                                                   \
        }                                                                       \
    } while (0)

#define COMPUTE(st)                                                             \
    do {                                                                        \
        u32 _sb = smem_u32(sm_raw) + (st) * STAGE_B;                            \
        _Pragma("unroll")                                                       \
        for (int ks = 0; ks < 2; ks++) {                                        \
            u32 afr[2][4][4], bfr[2][2][4];                                     \
            _Pragma("unroll")                                                   \
            for (int s = 0; s < 2; s++)                                         \
                _Pragma("unroll")                                               \
                for (int tm = 0; tm < 4; tm++)                                  \
                    ldsm_x4(afr[s][tm][0], afr[s][tm][1],                       \
                            afr[s][tm][2], afr[s][tm][3],                       \
                            _sb + s * ARR_B +                                   \
                            (warp_m * 64 + tm * 16 + a_row) * RSTRIDE +         \
                            ks * 32 + a_kb);                                    \
            _Pragma("unroll")                                                   \
            for (int s = 0; s < 2; s++)                                         \
                _Pragma("unroll")                                               \
                for (int t2 = 0; t2 < 2; t2++)                                  \
                    ldsm_x4(bfr[s][t2][0], bfr[s][t2][1],                       \
                            bfr[s][t2][2], bfr[s][t2][3],                       \
                            _sb + (2 + s) * ARR_B +                             \
                            (warp_n * 32 + t2 * 16 + b_row) * RSTRIDE +         \
                            ks * 32 + b_kb);                                    \
            _Pragma("unroll")                                                   \
            for (int tm = 0; tm < 4; tm++)                                      \
                _Pragma("unroll")                                               \
                for (int tn = 0; tn < 4; tn++) {                                \
                    const u32* bh_ = &bfr[0][tn >> 1][(tn & 1) * 2];            \
                    const u32* bl_ = &bfr[1][tn >> 1][(tn & 1) * 2];            \
                    mma16816(cf[tm][tn], afr[0][tm], bh_);                      \
                    mma16816(cf[tm][tn], afr[0][tm], bl_);                      \
                    mma16816(cf[tm][tn], afr[1][tm], bh_);                      \
                }                                                               \
        }                                                                       \
    } while (0)

    const int NIT = K / 32;
    G_LOAD(0, 0);
    CP_COMMIT();
    for (int it = 0; it < NIT; it++) {
        if (it + 1 < NIT) {
            G_LOAD((it + 1) & 1, (it + 1) * 32);
            CP_COMMIT();
            CP_WAIT1();
        } else {
            CP_WAIT0();
        }
        __syncthreads();
        COMPUTE(it & 1);
        __syncthreads();
    }

    // epilogue
    const int mrow = lane >> 2, ncol = (lane & 3) * 2;
#pragma unroll
    for (int tm = 0; tm < 4; tm++) {
#pragma unroll
        for (int tn = 0; tn < 4; tn++) {
            int r = m0 + warp_m * 64 + tm * 16 + mrow;
            int c = n0 + warp_n * 32 + tn * 8 + ncol;
            float2 bb = *(const float2*)&bias[c];
            float2 v0 = make_float2(cf[tm][tn][0] + bb.x, cf[tm][tn][1] + bb.y);
            float2 v1 = make_float2(cf[tm][tn][2] + bb.x, cf[tm][tn][3] + bb.y);
            *(float2*)&C[(size_t)r * N + c] = v0;
            *(float2*)&C[(size_t)(r + 8) * N + c] = v1;
        }
    }
#undef G_LOAD
#undef COMPUTE
}

// ---------------- flash attention (fp32, round-2 version) -------------------
__global__ void __launch_bounds__(256) flash_attn_kernel(
    const float* __restrict__ qkv, float* __restrict__ out)
{
    float* fa = (float*)sm_raw;
    float* Qt = fa;
    float* Kt = fa + 64 * 68;
    float* Vs = fa + 2 * 64 * 68;
    float* Ps = fa + 3 * 64 * 68;

    const int tid = threadIdx.x;
    const int ty = tid >> 4, tx = tid & 15;
    const int qt = blockIdx.x;
    const int b = blockIdx.y >> 4;
    const int h = blockIdx.y & 15;

    const float* qb = qkv + (size_t)b * T_SZ * C3 + h * HD;
    const float* kb = qb + C_DIM;
    const float* vb = qb + 2 * C_DIM;

    {
        const int i_base = tid >> 6;
        const int d = tid & 63;
#pragma unroll
        for (int r = 0; r < 16; r++) {
            int i = r * 4 + i_base;
            Qt[d * 68 + i] = qb[(size_t)(qt * 64 + i) * C3 + d] * (ATT_SCALE * LOG2E);
        }
    }

    float m_[4], l_[4], o_[4][4];
#pragma unroll
    for (int u = 0; u < 4; u++) {
        m_[u] = -CUDART_INF_F; l_[u] = 0.f;
#pragma unroll
        for (int v = 0; v < 4; v++) o_[u][v] = 0.f;
    }

    for (int st = 0; st < T_SZ / 64; st++) {
        __syncthreads();
        {
            const int j_base = tid >> 6;
            const int d = tid & 63;
#pragma unroll
            for (int r = 0; r < 16; r++) {
                int j = r * 4 + j_base;
                Kt[d * 68 + j] = kb[(size_t)(st * 64 + j) * C3 + d];
                Vs[j * 68 + d] = vb[(size_t)(st * 64 + j) * C3 + d];
            }
        }
        __syncthreads();

        float s[4][4] = {};
#pragma unroll
        for (int d = 0; d < 64; d++) {
            float4 qa = *(const float4*)&Qt[d * 68 + ty * 4];
            float4 ka = *(const float4*)&Kt[d * 68 + tx * 4];
            float qv[4] = {qa.x, qa.y, qa.z, qa.w};
            float kv[4] = {ka.x, ka.y, ka.z, ka.w};
#pragma unroll
            for (int u = 0; u < 4; u++)
#pragma unroll
                for (int v = 0; v < 4; v++)
                    s[u][v] += qv[u] * kv[v];
        }

#pragma unroll
        for (int u = 0; u < 4; u++) {
            float mt = fmaxf(fmaxf(s[u][0], s[u][1]), fmaxf(s[u][2], s[u][3]));
#pragma unroll
            for (int msk = 1; msk < 16; msk <<= 1)
                mt = fmaxf(mt, __shfl_xor_sync(0xffffffffu, mt, msk));
            float mn = fmaxf(m_[u], mt);
            float f = fast_exp2(m_[u] - mn);
            float p0 = fast_exp2(s[u][0] - mn);
            float p1 = fast_exp2(s[u][1] - mn);
            float p2 = fast_exp2(s[u][2] - mn);
            float p3 = fast_exp2(s[u][3] - mn);
            float rs = p0 + p1 + p2 + p3;
#pragma unroll
            for (int msk = 1; msk < 16; msk <<= 1)
                rs += __shfl_xor_sync(0xffffffffu, rs, msk);
            l_[u] = l_[u] * f + rs;
            m_[u] = mn;
#pragma unroll
            for (int v = 0; v < 4; v++) o_[u][v] *= f;
            *(float4*)&Ps[(ty * 4 + u) * 68 + tx * 4] = make_float4(p0, p1, p2, p3);
        }
        __syncthreads();

#pragma unroll 4
        for (int j = 0; j < 64; j++) {
            float4 vv = *(const float4*)&Vs[j * 68 + tx * 4];
            float vr[4] = {vv.x, vv.y, vv.z, vv.w};
            float pa[4];
#pragma unroll
            for (int u = 0; u < 4; u++) pa[u] = Ps[(ty * 4 + u) * 68 + j];
#pragma unroll
            for (int u = 0; u < 4; u++)
#pragma unroll
                for (int v = 0; v < 4; v++)
                    o_[u][v] += pa[u] * vr[v];
        }
    }

#pragma unroll
    for (int u = 0; u < 4; u++) {
        int i = qt * 64 + ty * 4 + u;
        float inv = 1.f / l_[u];
        float4 ov = make_float4(o_[u][0] * inv, o_[u][1] * inv,
                                o_[u][2] * inv, o_[u][3] * inv);
        *(float4*)&out[((size_t)b * T_SZ + i) * C_DIM + h * HD + tx * 4] = ov;
    }
}

// ---------------------------------------------------------------------------
extern "C" void kernel_launch(void* const* d_in, const int* in_sizes, int n_in,
                              void* d_out, int out_size)
{
    const float* x     = (const float*)d_in[0];
    const float* Wqkv  = (const float*)d_in[1];
    const float* bqkv  = (const float*)d_in[2];
    const float* Wproj = (const float*)d_in[3];
    const float* bproj = (const float*)d_in[4];
    float* out = (float*)d_out;

    float* qkv;  cudaGetSymbolAddress((void**)&qkv,  g_qkv);
    float* attn; cudaGetSymbolAddress((void**)&attn, g_attn);
    __nv_bfloat16 *xh, *xl, *ah, *al, *wqh, *wql, *wph, *wpl;
    cudaGetSymbolAddress((void**)&xh, g_xh);   cudaGetSymbolAddress((void**)&xl, g_xl);
    cudaGetSymbolAddress((void**)&ah, g_ah);   cudaGetSymbolAddress((void**)&al, g_al);
    cudaGetSymbolAddress((void**)&wqh, g_wqh); cudaGetSymbolAddress((void**)&wql, g_wql);
    cudaGetSymbolAddress((void**)&wph, g_wph); cudaGetSymbolAddress((void**)&wpl, g_wpl);

    const int FA_SMEM = 4 * 64 * 68 * (int)sizeof(float);  // 69632
    cudaFuncSetAttribute(flash_attn_kernel,
                         cudaFuncAttributeMaxDynamicSharedMemorySize, FA_SMEM);
    cudaFuncSetAttribute(gemm_mma_kernel,
                         cudaFuncAttributeMaxDynamicSharedMemorySize, GSMEM);

    // prep
    split_kernel<<<(M_ROWS * C_DIM / 4 + 255) / 256, 256>>>(x, xh, xl, M_ROWS * C_DIM / 4);
    transpose_split_kernel<<<dim3(C3 / 32, C_DIM / 32), dim3(32, 8)>>>(Wqkv, wqh, wql, C_DIM, C3);
    transpose_split_kernel<<<dim3(C_DIM / 32, C_DIM / 32), dim3(32, 8)>>>(Wproj, wph, wpl, C_DIM, C_DIM);

    // 1) qkv = x @ Wqkv + bqkv
    gemm_mma_kernel<<<dim3(C3 / 128, M_ROWS / 128), 256, GSMEM>>>(
        xh, xl, wqh, wql, bqkv, qkv, M_ROWS, C3, C_DIM);

    // 2) attention
    flash_attn_kernel<<<dim3(T_SZ / 64, B_SZ * NH), 256, FA_SMEM>>>(qkv, attn);

    // 3) out = attn @ Wproj + bproj
    split_kernel<<<(M_ROWS * C_DIM / 4 + 255) / 256, 256>>>(attn, ah, al, M_ROWS * C_DIM / 4);
    gemm_mma_kernel<<<dim3(C_DIM / 128, M_ROWS / 128), 256, GSMEM>>>(
        ah, al, wph, wpl, bproj, out, M_ROWS, C_DIM, C_DIM);
}

// round 5
// speedup vs baseline: 2.8005x; 1.9570x over previous
#include <cuda_runtime.h>
#include <cuda_bf16.h>
#include <math_constants.h>

#define C_DIM 1024
#define C3    3072
#define NH    16
#define HD    64
#define B_SZ  2
#define T_SZ  2048
#define M_ROWS (B_SZ*T_SZ)

#define ATT_SCALE 0.5f
#define LOG2E 1.4426950408889634f

typedef unsigned long long u64;
typedef unsigned int u32;

// ---------------- scratch (no device allocation allowed) -------------------
__device__ __nv_bfloat16 g_qh[(size_t)M_ROWS * C_DIM];
__device__ __nv_bfloat16 g_ql[(size_t)M_ROWS * C_DIM];
__device__ __nv_bfloat16 g_kh[(size_t)M_ROWS * C_DIM];
__device__ __nv_bfloat16 g_kl[(size_t)M_ROWS * C_DIM];
__device__ __nv_bfloat16 g_vh[(size_t)M_ROWS * C_DIM];
__device__ __nv_bfloat16 g_vl[(size_t)M_ROWS * C_DIM];
__device__ __nv_bfloat16 g_xh[(size_t)M_ROWS * C_DIM];
__device__ __nv_bfloat16 g_xl[(size_t)M_ROWS * C_DIM];
__device__ __nv_bfloat16 g_ah[(size_t)M_ROWS * C_DIM];
__device__ __nv_bfloat16 g_al[(size_t)M_ROWS * C_DIM];
__device__ __nv_bfloat16 g_wqh[(size_t)C3 * C_DIM];   // Wqkv^T hi [N][K]
__device__ __nv_bfloat16 g_wql[(size_t)C3 * C_DIM];
__device__ __nv_bfloat16 g_wph[(size_t)C_DIM * C_DIM];
__device__ __nv_bfloat16 g_wpl[(size_t)C_DIM * C_DIM];

// ---------------- helpers ----------------------------------------------------
__device__ __forceinline__ u32 smem_u32(const void* p) {
    u32 a; asm("{ .reg .u64 t; cvta.to.shared.u64 t, %1; cvt.u32.u64 %0, t; }"
               : "=r"(a) : "l"(p));
    return a;
}
__device__ __forceinline__ void ldsm_x4(u32& r0, u32& r1, u32& r2, u32& r3, u32 a) {
    asm volatile("ldmatrix.sync.aligned.m8n8.x4.shared.b16 {%0,%1,%2,%3}, [%4];"
                 : "=r"(r0), "=r"(r1), "=r"(r2), "=r"(r3) : "r"(a));
}
__device__ __forceinline__ void ldsm_x4t(u32& r0, u32& r1, u32& r2, u32& r3, u32 a) {
    asm volatile("ldmatrix.sync.aligned.m8n8.x4.trans.shared.b16 {%0,%1,%2,%3}, [%4];"
                 : "=r"(r0), "=r"(r1), "=r"(r2), "=r"(r3) : "r"(a));
}
__device__ __forceinline__ void mma16816(float* c, const u32* a, const u32* b) {
    asm volatile(
        "mma.sync.aligned.m16n8k16.row.col.f32.bf16.bf16.f32 "
        "{%0,%1,%2,%3},{%4,%5,%6,%7},{%8,%9},{%0,%1,%2,%3};"
        : "+f"(c[0]), "+f"(c[1]), "+f"(c[2]), "+f"(c[3])
        : "r"(a[0]), "r"(a[1]), "r"(a[2]), "r"(a[3]), "r"(b[0]), "r"(b[1]));
}
__device__ __forceinline__ float fast_exp2(float x) {
    float r; asm("ex2.approx.ftz.f32 %0, %1;" : "=f"(r) : "f"(x)); return r;
}
__device__ __forceinline__ u32 cvt_bf16x2(float lo, float hi) {
    u32 r; asm("cvt.rn.bf16x2.f32 %0, %1, %2;" : "=r"(r) : "f"(hi), "f"(lo));
    return r;
}
// split (f0,f1) fp32 pair into bf16x2 hi part and bf16x2 residual part
__device__ __forceinline__ void split2(float f0, float f1, u32& hi, u32& lo) {
    hi = cvt_bf16x2(f0, f1);
    float h0 = __uint_as_float(hi << 16);
    float h1 = __uint_as_float(hi & 0xffff0000u);
    lo = cvt_bf16x2(f0 - h0, f1 - h1);
}
#define CP_ASYNC16(d, s) asm volatile("cp.async.cg.shared.global [%0], [%1], 16;" :: "r"(d), "l"(s))
#define CP_COMMIT()      asm volatile("cp.async.commit_group;" ::: "memory")
#define CP_WAIT1()       asm volatile("cp.async.wait_group 1;" ::: "memory")
#define CP_WAIT0()       asm volatile("cp.async.wait_group 0;" ::: "memory")

// ---------------- prep: fp32 -> bf16 hi/lo split ----------------------------
__global__ void split_kernel(const float* __restrict__ in,
                             __nv_bfloat16* __restrict__ hi,
                             __nv_bfloat16* __restrict__ lo, int n4)
{
    int i = blockIdx.x * blockDim.x + threadIdx.x;
    if (i >= n4) return;
    float4 v = ((const float4*)in)[i];
    u32 h0, l0, h1, l1;
    split2(v.x, v.y, h0, l0);
    split2(v.z, v.w, h1, l1);
    ((uint2*)hi)[i] = make_uint2(h0, h1);
    ((uint2*)lo)[i] = make_uint2(l0, l1);
}

// ---------------- prep: W[K][N] -> W^T hi/lo [N][K] -------------------------
__global__ void transpose_split_kernel(const float* __restrict__ W,
                                       __nv_bfloat16* __restrict__ Wh,
                                       __nv_bfloat16* __restrict__ Wl,
                                       int K, int N)
{
    __shared__ float ts[32][33];
    int n0 = blockIdx.x * 32, k0 = blockIdx.y * 32;
    int tx = threadIdx.x, ty = threadIdx.y;  // 32 x 8
#pragma unroll
    for (int r = 0; r < 4; r++)
        ts[ty + 8 * r][tx] = W[(size_t)(k0 + ty + 8 * r) * N + n0 + tx];
    __syncthreads();
#pragma unroll
    for (int r = 0; r < 4; r++) {
        float v = ts[tx][ty + 8 * r];
        __nv_bfloat16 h = __float2bfloat16(v);
        __nv_bfloat16 l = __float2bfloat16(v - __bfloat162float(h));
        size_t o = (size_t)(n0 + ty + 8 * r) * K + k0 + tx;
        Wh[o] = h; Wl[o] = l;
    }
}

// ---------------- warp-MMA bf16x3 GEMM --------------------------------------
// C = (Ah+Al) @ (Bh+Bl)^T + bias   (Al*Bl dropped)
// SPLIT=0: fp32 C out.  SPLIT=1: write bf16 hi/lo into q/k/v buffers by part.
#define RSTRIDE 80
#define ARR_B   (128 * RSTRIDE)
#define STAGE_B (4 * ARR_B)
#define GSMEM   (2 * STAGE_B)

extern __shared__ char sm_raw[];

template<int SPLIT>
__global__ void __launch_bounds__(256) gemm_mma_kernel(
    const __nv_bfloat16* __restrict__ Ah, const __nv_bfloat16* __restrict__ Al,
    const __nv_bfloat16* __restrict__ Bh, const __nv_bfloat16* __restrict__ Bl,
    const float* __restrict__ bias, float* __restrict__ C,
    int M, int N, int K,
    __nv_bfloat16* oq_h, __nv_bfloat16* oq_l,
    __nv_bfloat16* ok_h, __nv_bfloat16* ok_l,
    __nv_bfloat16* ov_h, __nv_bfloat16* ov_l)
{
    const int tid = threadIdx.x, lane = tid & 31, wid = tid >> 5;
    const int warp_m = wid & 1, warp_n = wid >> 1;
    const int m0 = blockIdx.y * 128, n0 = blockIdx.x * 128;

    const int grp = lane >> 3, lrow = lane & 7;
    const int a_row = (grp & 1) * 8 + lrow, a_kb = (grp >> 1) * 16;
    const int b_row = (grp >> 1) * 8 + lrow, b_kb = (grp & 1) * 16;

    const __nv_bfloat16* srcs[4] = {Ah, Al, Bh, Bl};
    const int r0s[4] = {m0, m0, n0, n0};

    float cf[4][4][4];
#pragma unroll
    for (int tm = 0; tm < 4; tm++)
#pragma unroll
        for (int tn = 0; tn < 4; tn++)
#pragma unroll
            for (int q = 0; q < 4; q++) cf[tm][tn][q] = 0.f;

#define G_LOAD(st, k0v)                                                         \
    do {                                                                        \
        char* _b = sm_raw + (st) * STAGE_B;                                     \
        _Pragma("unroll")                                                       \
        for (int t = 0; t < 4; t++) {                                           \
            const __nv_bfloat16* _s = srcs[t] + (size_t)r0s[t] * K + (k0v);     \
            _Pragma("unroll")                                                   \
            for (int j = 0; j < 2; j++) {                                       \
                int _i = tid + j * 256;                                         \
                int _r = _i >> 2, _c = _i & 3;                                  \
                u32 _d = smem_u32(_b + t * ARR_B + _r * RSTRIDE + _c * 16);     \
                CP_ASYNC16(_d, _s + (size_t)_r * K + _c * 8);                   \
            }                                                                   \
        }                                                                       \
    } while (0)

#define COMPUTE(st)                                                             \
    do {                                                                        \
        u32 _sb = smem_u32(sm_raw) + (st) * STAGE_B;                            \
        _Pragma("unroll")                                                       \
        for (int ks = 0; ks < 2; ks++) {                                        \
            u32 afr[2][4][4], bfr[2][2][4];                                     \
            _Pragma("unroll")                                                   \
            for (int s = 0; s < 2; s++)                                         \
                _Pragma("unroll")                                               \
                for (int tm = 0; tm < 4; tm++)                                  \
                    ldsm_x4(afr[s][tm][0], afr[s][tm][1],                       \
                            afr[s][tm][2], afr[s][tm][3],                       \
                            _sb + s * ARR_B +                                   \
                            (warp_m * 64 + tm * 16 + a_row) * RSTRIDE +         \
                            ks * 32 + a_kb);                                    \
            _Pragma("unroll")                                                   \
            for (int s = 0; s < 2; s++)                                         \
                _Pragma("unroll")                                               \
                for (int t2 = 0; t2 < 2; t2++)                                  \
                    ldsm_x4(bfr[s][t2][0], bfr[s][t2][1],                       \
                            bfr[s][t2][2], bfr[s][t2][3],                       \
                            _sb + (2 + s) * ARR_B +                             \
                            (warp_n * 32 + t2 * 16 + b_row) * RSTRIDE +         \
                            ks * 32 + b_kb);                                    \
            _Pragma("unroll")                                                   \
            for (int tm = 0; tm < 4; tm++)                                      \
                _Pragma("unroll")                                               \
                for (int tn = 0; tn < 4; tn++) {                                \
                    const u32* bh_ = &bfr[0][tn >> 1][(tn & 1) * 2];            \
                    const u32* bl_ = &bfr[1][tn >> 1][(tn & 1) * 2];            \
                    mma16816(cf[tm][tn], afr[0][tm], bh_);                      \
                    mma16816(cf[tm][tn], afr[0][tm], bl_);                      \
                    mma16816(cf[tm][tn], afr[1][tm], bh_);                      \
                }                                                               \
        }                                                                       \
    } while (0)

    const int NIT = K / 32;
    G_LOAD(0, 0);
    CP_COMMIT();
    for (int it = 0; it < NIT; it++) {
        if (it + 1 < NIT) {
            G_LOAD((it + 1) & 1, (it + 1) * 32);
            CP_COMMIT();
            CP_WAIT1();
        } else {
            CP_WAIT0();
        }
        __syncthreads();
        COMPUTE(it & 1);
        __syncthreads();
    }

    const int mrow = lane >> 2, ncol = (lane & 3) * 2;
    if (SPLIT) {
        int part = n0 >> 10;
        __nv_bfloat16* dh = part == 0 ? oq_h : (part == 1 ? ok_h : ov_h);
        __nv_bfloat16* dl = part == 0 ? oq_l : (part == 1 ? ok_l : ov_l);
#pragma unroll
        for (int tm = 0; tm < 4; tm++)
#pragma unroll
            for (int tn = 0; tn < 4; tn++) {
                int r = m0 + warp_m * 64 + tm * 16 + mrow;
                int c = n0 + warp_n * 32 + tn * 8 + ncol;
                int lc = c & 1023;
                float2 bb = *(const float2*)&bias[c];
                u32 h0, l0, h1, l1;
                split2(cf[tm][tn][0] + bb.x, cf[tm][tn][1] + bb.y, h0, l0);
                split2(cf[tm][tn][2] + bb.x, cf[tm][tn][3] + bb.y, h1, l1);
                *(u32*)(dh + (size_t)r * C_DIM + lc) = h0;
                *(u32*)(dl + (size_t)r * C_DIM + lc) = l0;
                *(u32*)(dh + (size_t)(r + 8) * C_DIM + lc) = h1;
                *(u32*)(dl + (size_t)(r + 8) * C_DIM + lc) = l1;
            }
    } else {
#pragma unroll
        for (int tm = 0; tm < 4; tm++)
#pragma unroll
            for (int tn = 0; tn < 4; tn++) {
                int r = m0 + warp_m * 64 + tm * 16 + mrow;
                int c = n0 + warp_n * 32 + tn * 8 + ncol;
                float2 bb = *(const float2*)&bias[c];
                *(float2*)&C[(size_t)r * N + c] =
                    make_float2(cf[tm][tn][0] + bb.x, cf[tm][tn][1] + bb.y);
                *(float2*)&C[(size_t)(r + 8) * N + c] =
                    make_float2(cf[tm][tn][2] + bb.x, cf[tm][tn][3] + bb.y);
            }
    }
#undef G_LOAD
#undef COMPUTE
}

// ---------------- tensor-core flash attention -------------------------------
// CTA: 128 q rows of one (b,h); 8 warps, warp w owns rows w*16..w*16+15.
// K loop: 16 tiles of 128 kv rows, 2-stage cp.async double buffer.
// S = (Qh+Ql)(Kh+Kl)^T, P = softmax (exp2 domain), O += (Ph+Pl)(Vh+Vl).
#define FA_RS   72                 // smem row stride in bf16 elems (144 B)
#define FA_ARR  (128 * FA_RS)      // elems per [128][64] array (padded)
#define FA_ST0  (2 * FA_ARR)
#define FA_STSZ (4 * FA_ARR)
#define FA_SMEM ((2 * FA_ARR + 2 * FA_STSZ) * 2)   // 184320 B

__global__ void __launch_bounds__(256) flash_attn_mma(
    const __nv_bfloat16* __restrict__ qh, const __nv_bfloat16* __restrict__ ql,
    const __nv_bfloat16* __restrict__ kh, const __nv_bfloat16* __restrict__ kl,
    const __nv_bfloat16* __restrict__ vh, const __nv_bfloat16* __restrict__ vl,
    __nv_bfloat16* __restrict__ oh, __nv_bfloat16* __restrict__ ol)
{
    __nv_bfloat16* sm = (__nv_bfloat16*)sm_raw;
    const int tid = threadIdx.x, lane = tid & 31, w = tid >> 5;
    const int qt = blockIdx.x;
    const int b = blockIdx.y >> 4, h = blockIdx.y & 15;
    const size_t rowbase = (size_t)b * T_SZ;
    const int colbase = h * HD;

    const __nv_bfloat16* kvsrc[4] = {kh, kl, vh, vl};

#define FA_LOAD(st, kt)                                                         \
    do {                                                                        \
        _Pragma("unroll")                                                       \
        for (int a4 = 0; a4 < 4; a4++) {                                        \
            _Pragma("unroll")                                                   \
            for (int j = 0; j < 4; j++) {                                       \
                int idx = tid + j * 256;                                        \
                int r = idx >> 3, c8 = idx & 7;                                 \
                u32 d = smem_u32(sm + FA_ST0 + (st) * FA_STSZ + a4 * FA_ARR +   \
                                 r * FA_RS + c8 * 8);                           \
                CP_ASYNC16(d, kvsrc[a4] +                                       \
                           (rowbase + (kt) * 128 + r) * C_DIM + colbase + c8 * 8); \
            }                                                                   \
        }                                                                       \
    } while (0)

    FA_LOAD(0, 0);
    CP_COMMIT();

    // stage Q (hi, lo)
    {
        const __nv_bfloat16* qsrc[2] = {qh, ql};
#pragma unroll
        for (int a2 = 0; a2 < 2; a2++)
#pragma unroll
            for (int j = 0; j < 4; j++) {
                int idx = tid + j * 256;
                int r = idx >> 3, c8 = idx & 7;
                uint4 v = *(const uint4*)(qsrc[a2] +
                    (rowbase + qt * 128 + r) * C_DIM + colbase + c8 * 8);
                *(uint4*)(sm + a2 * FA_ARR + r * FA_RS + c8 * 8) = v;
            }
    }
    __syncthreads();

    // per-warp Q A-fragments (hoisted out of KV loop)
    u32 qfh[4][4], qfl[4][4];
    {
        u32 qbase = smem_u32(sm);
        int arow = w * 16 + (lane & 15);
        int acol = (lane >> 4) * 8;
#pragma unroll
        for (int ks = 0; ks < 4; ks++) {
            u32 off = (arow * FA_RS + ks * 16 + acol) * 2;
            ldsm_x4(qfh[ks][0], qfh[ks][1], qfh[ks][2], qfh[ks][3], qbase + off);
            ldsm_x4(qfl[ks][0], qfl[ks][1], qfl[ks][2], qfl[ks][3],
                    qbase + FA_ARR * 2 + off);
        }
    }

    float sf[16][4];
    float of[8][4];
#pragma unroll
    for (int j = 0; j < 8; j++)
#pragma unroll
        for (int q = 0; q < 4; q++) of[j][q] = 0.f;
    float m0 = -CUDART_INF_F, m1 = -CUDART_INF_F, l0 = 0.f, l1 = 0.f;

    const u32 sbase = smem_u32(sm);
    const int krow = (lane & 7) + ((lane >> 4) << 3);
    const int kch  = (lane >> 3) & 1;
    const int vrow = (lane & 7) + (((lane >> 3) & 1) << 3);
    const int vch  = lane >> 4;
    const float sc = ATT_SCALE * LOG2E;

    for (int kt = 0; kt < T_SZ / 128; kt++) {
        if (kt + 1 < T_SZ / 128) { FA_LOAD((kt + 1) & 1, kt + 1); CP_COMMIT(); CP_WAIT1(); }
        else CP_WAIT0();
        __syncthreads();
        u32 stb = sbase + (FA_ST0 + (kt & 1) * FA_STSZ) * 2;

        // ---- S = Q K^T (bf16x3) ----
#pragma unroll
        for (int j = 0; j < 16; j++) {
            sf[j][0] = 0.f; sf[j][1] = 0.f; sf[j][2] = 0.f; sf[j][3] = 0.f;
        }
#pragma unroll
        for (int js = 0; js < 8; js++) {
#pragma unroll
            for (int ks = 0; ks < 4; ks++) {
                u32 off = ((js * 16 + krow) * FA_RS + ks * 16 + kch * 8) * 2;
                u32 bh[4], bl[4];
                ldsm_x4(bh[0], bh[1], bh[2], bh[3], stb + off);
                ldsm_x4(bl[0], bl[1], bl[2], bl[3], stb + FA_ARR * 2 + off);
                mma16816(sf[2 * js],     qfh[ks], &bh[0]);
                mma16816(sf[2 * js],     qfh[ks], &bl[0]);
                mma16816(sf[2 * js],     qfl[ks], &bh[0]);
                mma16816(sf[2 * js + 1], qfh[ks], &bh[2]);
                mma16816(sf[2 * js + 1], qfh[ks], &bl[2]);
                mma16816(sf[2 * js + 1], qfl[ks], &bh[2]);
            }
        }

        // ---- online softmax (rows g and g+8, quad-reduced) ----
        float mt0 = -CUDART_INF_F, mt1 = -CUDART_INF_F;
#pragma unroll
        for (int j = 0; j < 16; j++) {
            sf[j][0] *= sc; sf[j][1] *= sc; sf[j][2] *= sc; sf[j][3] *= sc;
            mt0 = fmaxf(mt0, fmaxf(sf[j][0], sf[j][1]));
            mt1 = fmaxf(mt1, fmaxf(sf[j][2], sf[j][3]));
        }
        mt0 = fmaxf(mt0, __shfl_xor_sync(0xffffffffu, mt0, 1));
        mt0 = fmaxf(mt0, __shfl_xor_sync(0xffffffffu, mt0, 2));
        mt1 = fmaxf(mt1, __shfl_xor_sync(0xffffffffu, mt1, 1));
        mt1 = fmaxf(mt1, __shfl_xor_sync(0xffffffffu, mt1, 2));
        float mn0 = fmaxf(m0, mt0), mn1 = fmaxf(m1, mt1);
        float f0 = fast_exp2(m0 - mn0), f1 = fast_exp2(m1 - mn1);
        m0 = mn0; m1 = mn1;
        float rs0 = 0.f, rs1 = 0.f;
#pragma unroll
        for (int j = 0; j < 16; j++) {
            sf[j][0] = fast_exp2(sf[j][0] - mn0);
            sf[j][1] = fast_exp2(sf[j][1] - mn0);
            sf[j][2] = fast_exp2(sf[j][2] - mn1);
            sf[j][3] = fast_exp2(sf[j][3] - mn1);
            rs0 += sf[j][0] + sf[j][1];
            rs1 += sf[j][2] + sf[j][3];
        }
        rs0 += __shfl_xor_sync(0xffffffffu, rs0, 1);
        rs0 += __shfl_xor_sync(0xffffffffu, rs0, 2);
        rs1 += __shfl_xor_sync(0xffffffffu, rs1, 1);
        rs1 += __shfl_xor_sync(0xffffffffu, rs1, 2);
        l0 = l0 * f0 + rs0;
        l1 = l1 * f1 + rs1;
#pragma unroll
        for (int j = 0; j < 8; j++) {
            of[j][0] *= f0; of[j][1] *= f0; of[j][2] *= f1; of[j][3] *= f1;
        }

        // ---- O += P V (bf16x3), P straight from S fragments ----
#pragma unroll
        for (int kp = 0; kp < 8; kp++) {
            u32 ah[4], al[4];
            split2(sf[2 * kp][0],     sf[2 * kp][1],     ah[0], al[0]);
            split2(sf[2 * kp][2],     sf[2 * kp][3],     ah[1], al[1]);
            split2(sf[2 * kp + 1][0], sf[2 * kp + 1][1], ah[2], al[2]);
            split2(sf[2 * kp + 1][2], sf[2 * kp + 1][3], ah[3], al[3]);
#pragma unroll
            for (int dt = 0; dt < 4; dt++) {
                u32 off = ((kp * 16 + vrow) * FA_RS + dt * 16 + vch * 8) * 2;
                u32 bvh[4], bvl[4];
                ldsm_x4t(bvh[0], bvh[1], bvh[2], bvh[3], stb + 2 * FA_ARR * 2 + off);
                ldsm_x4t(bvl[0], bvl[1], bvl[2], bvl[3], stb + 3 * FA_ARR * 2 + off);
                mma16816(of[2 * dt],     ah, &bvh[0]);
                mma16816(of[2 * dt],     al, &bvh[0]);
                mma16816(of[2 * dt],     ah, &bvl[0]);
                mma16816(of[2 * dt + 1], ah, &bvh[2]);
                mma16816(of[2 * dt + 1], al, &bvh[2]);
                mma16816(of[2 * dt + 1], ah, &bvl[2]);
            }
        }
        __syncthreads();
    }

    // ---- epilogue: normalize, split to bf16 hi/lo ----
    float inv0 = 1.f / l0, inv1 = 1.f / l1;
    const int g = lane >> 2, t2 = (lane & 3) * 2;
    size_t r0 = rowbase + qt * 128 + w * 16 + g;
#pragma unroll
    for (int j = 0; j < 8; j++) {
        int c = colbase + j * 8 + t2;
        u32 h0, lo0, h1, lo1;
        split2(of[j][0] * inv0, of[j][1] * inv0, h0, lo0);
        split2(of[j][2] * inv1, of[j][3] * inv1, h1, lo1);
        *(u32*)(oh + r0 * C_DIM + c) = h0;
        *(u32*)(ol + r0 * C_DIM + c) = lo0;
        *(u32*)(oh + (r0 + 8) * C_DIM + c) = h1;
        *(u32*)(ol + (r0 + 8) * C_DIM + c) = lo1;
    }
#undef FA_LOAD
}

// ---------------------------------------------------------------------------
extern "C" void kernel_launch(void* const* d_in, const int* in_sizes, int n_in,
                              void* d_out, int out_size)
{
    const float* x     = (const float*)d_in[0];
    const float* Wqkv  = (const float*)d_in[1];
    const float* bqkv  = (const float*)d_in[2];
    const float* Wproj = (const float*)d_in[3];
    const float* bproj = (const float*)d_in[4];
    float* out = (float*)d_out;

    __nv_bfloat16 *qh, *ql, *kh, *kl, *vh, *vl, *xh, *xl, *ah, *al;
    __nv_bfloat16 *wqh, *wql, *wph, *wpl;
    cudaGetSymbolAddress((void**)&qh, g_qh);   cudaGetSymbolAddress((void**)&ql, g_ql);
    cudaGetSymbolAddress((void**)&kh, g_kh);   cudaGetSymbolAddress((void**)&kl, g_kl);
    cudaGetSymbolAddress((void**)&vh, g_vh);   cudaGetSymbolAddress((void**)&vl, g_vl);
    cudaGetSymbolAddress((void**)&xh, g_xh);   cudaGetSymbolAddress((void**)&xl, g_xl);
    cudaGetSymbolAddress((void**)&ah, g_ah);   cudaGetSymbolAddress((void**)&al, g_al);
    cudaGetSymbolAddress((void**)&wqh, g_wqh); cudaGetSymbolAddress((void**)&wql, g_wql);
    cudaGetSymbolAddress((void**)&wph, g_wph); cudaGetSymbolAddress((void**)&wpl, g_wpl);

    cudaFuncSetAttribute(gemm_mma_kernel<0>,
                         cudaFuncAttributeMaxDynamicSharedMemorySize, GSMEM);
    cudaFuncSetAttribute(gemm_mma_kernel<1>,
                         cudaFuncAttributeMaxDynamicSharedMemorySize, GSMEM);
    cudaFuncSetAttribute(flash_attn_mma,
                         cudaFuncAttributeMaxDynamicSharedMemorySize, FA_SMEM);

    // prep
    split_kernel<<<(M_ROWS * C_DIM / 4 + 255) / 256, 256>>>(x, xh, xl, M_ROWS * C_DIM / 4);
    transpose_split_kernel<<<dim3(C3 / 32, C_DIM / 32), dim3(32, 8)>>>(Wqkv, wqh, wql, C_DIM, C3);
    transpose_split_kernel<<<dim3(C_DIM / 32, C_DIM / 32), dim3(32, 8)>>>(Wproj, wph, wpl, C_DIM, C_DIM);

    // 1) qkv projection -> bf16 hi/lo q/k/v buffers directly
    gemm_mma_kernel<1><<<dim3(C3 / 128, M_ROWS / 128), 256, GSMEM>>>(
        xh, xl, wqh, wql, bqkv, nullptr, M_ROWS, C3, C_DIM,
        qh, ql, kh, kl, vh, vl);

    // 2) attention -> bf16 hi/lo
    flash_attn_mma<<<dim3(T_SZ / 128, B_SZ * NH), 256, FA_SMEM>>>(
        qh, ql, kh, kl, vh, vl, ah, al);

    // 3) out = attn @ Wproj + bproj (fp32 out)
    gemm_mma_kernel<0><<<dim3(C_DIM / 128, M_ROWS / 128), 256, GSMEM>>>(
        ah, al, wph, wpl, bproj, out, M_ROWS, C_DIM, C_DIM,
        nullptr, nullptr, nullptr, nullptr, nullptr, nullptr);
}

// round 6
// speedup vs baseline: 2.8437x; 1.0154x over previous
#include <cuda_runtime.h>
#include <cuda_bf16.h>
#include <math_constants.h>

#define C_DIM 1024
#define C3    3072
#define NH    16
#define HD    64
#define B_SZ  2
#define T_SZ  2048
#define M_ROWS (B_SZ*T_SZ)

#define ATT_SCALE 0.5f
#define LOG2E 1.4426950408889634f

typedef unsigned long long u64;
typedef unsigned int u32;

// ---------------- scratch (no device allocation allowed) -------------------
__device__ __nv_bfloat16 g_qh[(size_t)M_ROWS * C_DIM];
__device__ __nv_bfloat16 g_ql[(size_t)M_ROWS * C_DIM];
__device__ __nv_bfloat16 g_kh[(size_t)M_ROWS * C_DIM];
__device__ __nv_bfloat16 g_kl[(size_t)M_ROWS * C_DIM];
__device__ __nv_bfloat16 g_vh[(size_t)M_ROWS * C_DIM];
__device__ __nv_bfloat16 g_vl[(size_t)M_ROWS * C_DIM];
__device__ __nv_bfloat16 g_xh[(size_t)M_ROWS * C_DIM];
__device__ __nv_bfloat16 g_xl[(size_t)M_ROWS * C_DIM];
__device__ __nv_bfloat16 g_ah[(size_t)M_ROWS * C_DIM];
__device__ __nv_bfloat16 g_al[(size_t)M_ROWS * C_DIM];
__device__ __nv_bfloat16 g_wqh[(size_t)C3 * C_DIM];   // Wqkv^T hi [N][K]
__device__ __nv_bfloat16 g_wql[(size_t)C3 * C_DIM];
__device__ __nv_bfloat16 g_wph[(size_t)C_DIM * C_DIM];
__device__ __nv_bfloat16 g_wpl[(size_t)C_DIM * C_DIM];

// ---------------- helpers ----------------------------------------------------
__device__ __forceinline__ u32 smem_u32(const void* p) {
    u32 a; asm("{ .reg .u64 t; cvta.to.shared.u64 t, %1; cvt.u32.u64 %0, t; }"
               : "=r"(a) : "l"(p));
    return a;
}
__device__ __forceinline__ void ldsm_x4(u32& r0, u32& r1, u32& r2, u32& r3, u32 a) {
    asm volatile("ldmatrix.sync.aligned.m8n8.x4.shared.b16 {%0,%1,%2,%3}, [%4];"
                 : "=r"(r0), "=r"(r1), "=r"(r2), "=r"(r3) : "r"(a));
}
__device__ __forceinline__ void ldsm_x4t(u32& r0, u32& r1, u32& r2, u32& r3, u32 a) {
    asm volatile("ldmatrix.sync.aligned.m8n8.x4.trans.shared.b16 {%0,%1,%2,%3}, [%4];"
                 : "=r"(r0), "=r"(r1), "=r"(r2), "=r"(r3) : "r"(a));
}
__device__ __forceinline__ void mma16816(float* c, const u32* a, const u32* b) {
    asm volatile(
        "mma.sync.aligned.m16n8k16.row.col.f32.bf16.bf16.f32 "
        "{%0,%1,%2,%3},{%4,%5,%6,%7},{%8,%9},{%0,%1,%2,%3};"
        : "+f"(c[0]), "+f"(c[1]), "+f"(c[2]), "+f"(c[3])
        : "r"(a[0]), "r"(a[1]), "r"(a[2]), "r"(a[3]), "r"(b[0]), "r"(b[1]));
}
__device__ __forceinline__ float fast_exp2(float x) {
    float r; asm("ex2.approx.ftz.f32 %0, %1;" : "=f"(r) : "f"(x)); return r;
}
__device__ __forceinline__ u32 cvt_bf16x2(float lo, float hi) {
    u32 r; asm("cvt.rn.bf16x2.f32 %0, %1, %2;" : "=r"(r) : "f"(hi), "f"(lo));
    return r;
}
__device__ __forceinline__ void split2(float f0, float f1, u32& hi, u32& lo) {
    hi = cvt_bf16x2(f0, f1);
    float h0 = __uint_as_float(hi << 16);
    float h1 = __uint_as_float(hi & 0xffff0000u);
    lo = cvt_bf16x2(f0 - h0, f1 - h1);
}
#define CP_ASYNC16(d, s) asm volatile("cp.async.cg.shared.global [%0], [%1], 16;" :: "r"(d), "l"(s))
#define CP_COMMIT()      asm volatile("cp.async.commit_group;" ::: "memory")
#define CP_WAIT1()       asm volatile("cp.async.wait_group 1;" ::: "memory")
#define CP_WAIT0()       asm volatile("cp.async.wait_group 0;" ::: "memory")

// ---------------- prep: fp32 -> bf16 hi/lo split ----------------------------
__global__ void split_kernel(const float* __restrict__ in,
                             __nv_bfloat16* __restrict__ hi,
                             __nv_bfloat16* __restrict__ lo, int n4)
{
    int i = blockIdx.x * blockDim.x + threadIdx.x;
    if (i >= n4) return;
    float4 v = ((const float4*)in)[i];
    u32 h0, l0, h1, l1;
    split2(v.x, v.y, h0, l0);
    split2(v.z, v.w, h1, l1);
    ((uint2*)hi)[i] = make_uint2(h0, h1);
    ((uint2*)lo)[i] = make_uint2(l0, l1);
}

// ---------------- prep: W[K][N] -> W^T hi/lo [N][K] -------------------------
__global__ void transpose_split_kernel(const float* __restrict__ W,
                                       __nv_bfloat16* __restrict__ Wh,
                                       __nv_bfloat16* __restrict__ Wl,
                                       int K, int N)
{
    __shared__ float ts[32][33];
    int n0 = blockIdx.x * 32, k0 = blockIdx.y * 32;
    int tx = threadIdx.x, ty = threadIdx.y;  // 32 x 8
#pragma unroll
    for (int r = 0; r < 4; r++)
        ts[ty + 8 * r][tx] = W[(size_t)(k0 + ty + 8 * r) * N + n0 + tx];
    __syncthreads();
#pragma unroll
    for (int r = 0; r < 4; r++) {
        float v = ts[tx][ty + 8 * r];
        __nv_bfloat16 h = __float2bfloat16(v);
        __nv_bfloat16 l = __float2bfloat16(v - __bfloat162float(h));
        size_t o = (size_t)(n0 + ty + 8 * r) * K + k0 + tx;
        Wh[o] = h; Wl[o] = l;
    }
}

// ---------------- warp-MMA bf16x3 GEMM --------------------------------------
// C = (Ah+Al) @ (Bh+Bl)^T + bias   (Al*Bl dropped)
// 128x128 CTA tile, BK=32, 4 warps (2m x 2n), each 64x64, 2-stage cp.async.
#define RSTRIDE 80
#define ARR_B   (128 * RSTRIDE)
#define STAGE_B (4 * ARR_B)
#define GSMEM   (2 * STAGE_B)

extern __shared__ char sm_raw[];

template<int SPLIT>
__global__ void __launch_bounds__(128) gemm_mma_kernel(
    const __nv_bfloat16* __restrict__ Ah, const __nv_bfloat16* __restrict__ Al,
    const __nv_bfloat16* __restrict__ Bh, const __nv_bfloat16* __restrict__ Bl,
    const float* __restrict__ bias, float* __restrict__ C,
    int M, int N, int K,
    __nv_bfloat16* oq_h, __nv_bfloat16* oq_l,
    __nv_bfloat16* ok_h, __nv_bfloat16* ok_l,
    __nv_bfloat16* ov_h, __nv_bfloat16* ov_l)
{
    const int tid = threadIdx.x, lane = tid & 31, wid = tid >> 5;
    const int warp_m = wid & 1, warp_n = wid >> 1;   // 2 x 2
    const int m0 = blockIdx.y * 128, n0 = blockIdx.x * 128;

    const int grp = lane >> 3, lrow = lane & 7;
    const int a_row = (grp & 1) * 8 + lrow, a_kb = (grp >> 1) * 16;
    const int b_row = (grp >> 1) * 8 + lrow, b_kb = (grp & 1) * 16;

    const __nv_bfloat16* srcs[4] = {Ah, Al, Bh, Bl};
    const int r0s[4] = {m0, m0, n0, n0};

    float cf[4][8][4];
#pragma unroll
    for (int tm = 0; tm < 4; tm++)
#pragma unroll
        for (int tn = 0; tn < 8; tn++)
#pragma unroll
            for (int q = 0; q < 4; q++) cf[tm][tn][q] = 0.f;

#define G_LOAD(st, k0v)                                                         \
    do {                                                                        \
        char* _b = sm_raw + (st) * STAGE_B;                                     \
        _Pragma("unroll")                                                       \
        for (int t = 0; t < 4; t++) {                                           \
            const __nv_bfloat16* _s = srcs[t] + (size_t)r0s[t] * K + (k0v);     \
            _Pragma("unroll")                                                   \
            for (int j = 0; j < 4; j++) {                                       \
                int _i = tid + j * 128;                                         \
                int _r = _i >> 2, _c = _i & 3;                                  \
                u32 _d = smem_u32(_b + t * ARR_B + _r * RSTRIDE + _c * 16);     \
                CP_ASYNC16(_d, _s + (size_t)_r * K + _c * 8);                   \
            }                                                                   \
        }                                                                       \
    } while (0)

#define COMPUTE(st)                                                             \
    do {                                                                        \
        u32 _sb = smem_u32(sm_raw) + (st) * STAGE_B;                            \
        _Pragma("unroll")                                                       \
        for (int ks = 0; ks < 2; ks++) {                                        \
            u32 afr[2][4][4], bfr[2][4][4];                                     \
            _Pragma("unroll")                                                   \
            for (int s = 0; s < 2; s++)                                         \
                _Pragma("unroll")                                               \
                for (int tm = 0; tm < 4; tm++)                                  \
                    ldsm_x4(afr[s][tm][0], afr[s][tm][1],                       \
                            afr[s][tm][2], afr[s][tm][3],                       \
                            _sb + s * ARR_B +                                   \
                            (warp_m * 64 + tm * 16 + a_row) * RSTRIDE +         \
                            ks * 32 + a_kb);                                    \
            _Pragma("unroll")                                                   \
            for (int s = 0; s < 2; s++)                                         \
                _Pragma("unroll")                                               \
                for (int t2 = 0; t2 < 4; t2++)                                  \
                    ldsm_x4(bfr[s][t2][0], bfr[s][t2][1],                       \
                            bfr[s][t2][2], bfr[s][t2][3],                       \
                            _sb + (2 + s) * ARR_B +                             \
                            (warp_n * 64 + t2 * 16 + b_row) * RSTRIDE +         \
                            ks * 32 + b_kb);                                    \
            _Pragma("unroll")                                                   \
            for (int tm = 0; tm < 4; tm++)                                      \
                _Pragma("unroll")                                               \
                for (int tn = 0; tn < 8; tn++) {                                \
                    const u32* bh_ = &bfr[0][tn >> 1][(tn & 1) * 2];            \
                    const u32* bl_ = &bfr[1][tn >> 1][(tn & 1) * 2];            \
                    mma16816(cf[tm][tn], afr[0][tm], bh_);                      \
                    mma16816(cf[tm][tn], afr[0][tm], bl_);                      \
                    mma16816(cf[tm][tn], afr[1][tm], bh_);                      \
                }                                                               \
        }                                                                       \
    } while (0)

    const int NIT = K / 32;
    G_LOAD(0, 0);
    CP_COMMIT();
    for (int it = 0; it < NIT; it++) {
        if (it + 1 < NIT) {
            G_LOAD((it + 1) & 1, (it + 1) * 32);
            CP_COMMIT();
            CP_WAIT1();
        } else {
            CP_WAIT0();
        }
        __syncthreads();
        COMPUTE(it & 1);
        __syncthreads();
    }

    const int mrow = lane >> 2, ncol = (lane & 3) * 2;
    if (SPLIT) {
        int part = n0 >> 10;
        __nv_bfloat16* dh = part == 0 ? oq_h : (part == 1 ? ok_h : ov_h);
        __nv_bfloat16* dl = part == 0 ? oq_l : (part == 1 ? ok_l : ov_l);
#pragma unroll
        for (int tm = 0; tm < 4; tm++)
#pragma unroll
            for (int tn = 0; tn < 8; tn++) {
                int r = m0 + warp_m * 64 + tm * 16 + mrow;
                int c = n0 + warp_n * 64 + tn * 8 + ncol;
                int lc = c & 1023;
                float2 bb = *(const float2*)&bias[c];
                u32 h0, l0, h1, l1;
                split2(cf[tm][tn][0] + bb.x, cf[tm][tn][1] + bb.y, h0, l0);
                split2(cf[tm][tn][2] + bb.x, cf[tm][tn][3] + bb.y, h1, l1);
                *(u32*)(dh + (size_t)r * C_DIM + lc) = h0;
                *(u32*)(dl + (size_t)r * C_DIM + lc) = l0;
                *(u32*)(dh + (size_t)(r + 8) * C_DIM + lc) = h1;
                *(u32*)(dl + (size_t)(r + 8) * C_DIM + lc) = l1;
            }
    } else {
#pragma unroll
        for (int tm = 0; tm < 4; tm++)
#pragma unroll
            for (int tn = 0; tn < 8; tn++) {
                int r = m0 + warp_m * 64 + tm * 16 + mrow;
                int c = n0 + warp_n * 64 + tn * 8 + ncol;
                float2 bb = *(const float2*)&bias[c];
                *(float2*)&C[(size_t)r * N + c] =
                    make_float2(cf[tm][tn][0] + bb.x, cf[tm][tn][1] + bb.y);
                *(float2*)&C[(size_t)(r + 8) * N + c] =
                    make_float2(cf[tm][tn][2] + bb.x, cf[tm][tn][3] + bb.y);
            }
    }
#undef G_LOAD
#undef COMPUTE
}

// ---------------- tensor-core flash attention -------------------------------
#define FA_RS   72
#define FA_ARR  (128 * FA_RS)
#define FA_ST0  (2 * FA_ARR)
#define FA_STSZ (4 * FA_ARR)
#define FA_SMEM ((2 * FA_ARR + 2 * FA_STSZ) * 2)   // 184320 B

__global__ void __launch_bounds__(256) flash_attn_mma(
    const __nv_bfloat16* __restrict__ qh, const __nv_bfloat16* __restrict__ ql,
    const __nv_bfloat16* __restrict__ kh, const __nv_bfloat16* __restrict__ kl,
    const __nv_bfloat16* __restrict__ vh, const __nv_bfloat16* __restrict__ vl,
    __nv_bfloat16* __restrict__ oh, __nv_bfloat16* __restrict__ ol)
{
    __nv_bfloat16* sm = (__nv_bfloat16*)sm_raw;
    const int tid = threadIdx.x, lane = tid & 31, w = tid >> 5;
    const int qt = blockIdx.x;
    const int b = blockIdx.y >> 4, h = blockIdx.y & 15;
    const size_t rowbase = (size_t)b * T_SZ;
    const int colbase = h * HD;

    const __nv_bfloat16* kvsrc[4] = {kh, kl, vh, vl};

#define FA_LOAD(st, kt)                                                         \
    do {                                                                        \
        _Pragma("unroll")                                                       \
        for (int a4 = 0; a4 < 4; a4++) {                                        \
            _Pragma("unroll")                                                   \
            for (int j = 0; j < 4; j++) {                                       \
                int idx = tid + j * 256;                                        \
                int r = idx >> 3, c8 = idx & 7;                                 \
                u32 d = smem_u32(sm + FA_ST0 + (st) * FA_STSZ + a4 * FA_ARR +   \
                                 r * FA_RS + c8 * 8);                           \
                CP_ASYNC16(d, kvsrc[a4] +                                       \
                           (rowbase + (kt) * 128 + r) * C_DIM + colbase + c8 * 8); \
            }                                                                   \
        }                                                                       \
    } while (0)

    FA_LOAD(0, 0);
    CP_COMMIT();

    {
        const __nv_bfloat16* qsrc[2] = {qh, ql};
#pragma unroll
        for (int a2 = 0; a2 < 2; a2++)
#pragma unroll
            for (int j = 0; j < 4; j++) {
                int idx = tid + j * 256;
                int r = idx >> 3, c8 = idx & 7;
                uint4 v = *(const uint4*)(qsrc[a2] +
                    (rowbase + qt * 128 + r) * C_DIM + colbase + c8 * 8);
                *(uint4*)(sm + a2 * FA_ARR + r * FA_RS + c8 * 8) = v;
            }
    }
    __syncthreads();

    u32 qfh[4][4], qfl[4][4];
    {
        u32 qbase = smem_u32(sm);
        int arow = w * 16 + (lane & 15);
        int acol = (lane >> 4) * 8;
#pragma unroll
        for (int ks = 0; ks < 4; ks++) {
            u32 off = (arow * FA_RS + ks * 16 + acol) * 2;
            ldsm_x4(qfh[ks][0], qfh[ks][1], qfh[ks][2], qfh[ks][3], qbase + off);
            ldsm_x4(qfl[ks][0], qfl[ks][1], qfl[ks][2], qfl[ks][3],
                    qbase + FA_ARR * 2 + off);
        }
    }

    float sf[16][4];
    float of[8][4];
#pragma unroll
    for (int j = 0; j < 8; j++)
#pragma unroll
        for (int q = 0; q < 4; q++) of[j][q] = 0.f;
    float m0 = -CUDART_INF_F, m1 = -CUDART_INF_F, l0 = 0.f, l1 = 0.f;

    const u32 sbase = smem_u32(sm);
    const int krow = (lane & 7) + ((lane >> 4) << 3);
    const int kch  = (lane >> 3) & 1;
    const int vrow = (lane & 7) + (((lane >> 3) & 1) << 3);
    const int vch  = lane >> 4;
    const float sc = ATT_SCALE * LOG2E;

    for (int kt = 0; kt < T_SZ / 128; kt++) {
        if (kt + 1 < T_SZ / 128) { FA_LOAD((kt + 1) & 1, kt + 1); CP_COMMIT(); CP_WAIT1(); }
        else CP_WAIT0();
        __syncthreads();
        u32 stb = sbase + (FA_ST0 + (kt & 1) * FA_STSZ) * 2;

#pragma unroll
        for (int j = 0; j < 16; j++) {
            sf[j][0] = 0.f; sf[j][1] = 0.f; sf[j][2] = 0.f; sf[j][3] = 0.f;
        }
#pragma unroll
        for (int js = 0; js < 8; js++) {
#pragma unroll
            for (int ks = 0; ks < 4; ks++) {
                u32 off = ((js * 16 + krow) * FA_RS + ks * 16 + kch * 8) * 2;
                u32 bh[4], bl[4];
                ldsm_x4(bh[0], bh[1], bh[2], bh[3], stb + off);
                ldsm_x4(bl[0], bl[1], bl[2], bl[3], stb + FA_ARR * 2 + off);
                mma16816(sf[2 * js],     qfh[ks], &bh[0]);
                mma16816(sf[2 * js],     qfh[ks], &bl[0]);
                mma16816(sf[2 * js],     qfl[ks], &bh[0]);
                mma16816(sf[2 * js + 1], qfh[ks], &bh[2]);
                mma16816(sf[2 * js + 1], qfh[ks], &bl[2]);
                mma16816(sf[2 * js + 1], qfl[ks], &bh[2]);
            }
        }

        float mt0 = -CUDART_INF_F, mt1 = -CUDART_INF_F;
#pragma unroll
        for (int j = 0; j < 16; j++) {
            sf[j][0] *= sc; sf[j][1] *= sc; sf[j][2] *= sc; sf[j][3] *= sc;
            mt0 = fmaxf(mt0, fmaxf(sf[j][0], sf[j][1]));
            mt1 = fmaxf(mt1, fmaxf(sf[j][2], sf[j][3]));
        }
        mt0 = fmaxf(mt0, __shfl_xor_sync(0xffffffffu, mt0, 1));
        mt0 = fmaxf(mt0, __shfl_xor_sync(0xffffffffu, mt0, 2));
        mt1 = fmaxf(mt1, __shfl_xor_sync(0xffffffffu, mt1, 1));
        mt1 = fmaxf(mt1, __shfl_xor_sync(0xffffffffu, mt1, 2));
        float mn0 = fmaxf(m0, mt0), mn1 = fmaxf(m1, mt1);
        float f0 = fast_exp2(m0 - mn0), f1 = fast_exp2(m1 - mn1);
        m0 = mn0; m1 = mn1;
        float rs0 = 0.f, rs1 = 0.f;
#pragma unroll
        for (int j = 0; j < 16; j++) {
            sf[j][0] = fast_exp2(sf[j][0] - mn0);
            sf[j][1] = fast_exp2(sf[j][1] - mn0);
            sf[j][2] = fast_exp2(sf[j][2] - mn1);
            sf[j][3] = fast_exp2(sf[j][3] - mn1);
            rs0 += sf[j][0] + sf[j][1];
            rs1 += sf[j][2] + sf[j][3];
        }
        rs0 += __shfl_xor_sync(0xffffffffu, rs0, 1);
        rs0 += __shfl_xor_sync(0xffffffffu, rs0, 2);
        rs1 += __shfl_xor_sync(0xffffffffu, rs1, 1);
        rs1 += __shfl_xor_sync(0xffffffffu, rs1, 2);
        l0 = l0 * f0 + rs0;
        l1 = l1 * f1 + rs1;
#pragma unroll
        for (int j = 0; j < 8; j++) {
            of[j][0] *= f0; of[j][1] *= f0; of[j][2] *= f1; of[j][3] *= f1;
        }

#pragma unroll
        for (int kp = 0; kp < 8; kp++) {
            u32 ah[4], al[4];
            split2(sf[2 * kp][0],     sf[2 * kp][1],     ah[0], al[0]);
            split2(sf[2 * kp][2],     sf[2 * kp][3],     ah[1], al[1]);
            split2(sf[2 * kp + 1][0], sf[2 * kp + 1][1], ah[2], al[2]);
            split2(sf[2 * kp + 1][2], sf[2 * kp + 1][3], ah[3], al[3]);
#pragma unroll
            for (int dt = 0; dt < 4; dt++) {
                u32 off = ((kp * 16 + vrow) * FA_RS + dt * 16 + vch * 8) * 2;
                u32 bvh[4], bvl[4];
                ldsm_x4t(bvh[0], bvh[1], bvh[2], bvh[3], stb + 2 * FA_ARR * 2 + off);
                ldsm_x4t(bvl[0], bvl[1], bvl[2], bvl[3], stb + 3 * FA_ARR * 2 + off);
                mma16816(of[2 * dt],     ah, &bvh[0]);
                mma16816(of[2 * dt],     al, &bvh[0]);
                mma16816(of[2 * dt],     ah, &bvl[0]);
                mma16816(of[2 * dt + 1], ah, &bvh[2]);
                mma16816(of[2 * dt + 1], al, &bvh[2]);
                mma16816(of[2 * dt + 1], ah, &bvl[2]);
            }
        }
        __syncthreads();
    }

    float inv0 = 1.f / l0, inv1 = 1.f / l1;
    const int g = lane >> 2, t2 = (lane & 3) * 2;
    size_t r0 = rowbase + qt * 128 + w * 16 + g;
#pragma unroll
    for (int j = 0; j < 8; j++) {
        int c = colbase + j * 8 + t2;
        u32 h0, lo0, h1, lo1;
        split2(of[j][0] * inv0, of[j][1] * inv0, h0, lo0);
        split2(of[j][2] * inv1, of[j][3] * inv1, h1, lo1);
        *(u32*)(oh + r0 * C_DIM + c) = h0;
        *(u32*)(ol + r0 * C_DIM + c) = lo0;
        *(u32*)(oh + (r0 + 8) * C_DIM + c) = h1;
        *(u32*)(ol + (r0 + 8) * C_DIM + c) = lo1;
    }
#undef FA_LOAD
}

// ---------------------------------------------------------------------------
extern "C" void kernel_launch(void* const* d_in, const int* in_sizes, int n_in,
                              void* d_out, int out_size)
{
    const float* x     = (const float*)d_in[0];
    const float* Wqkv  = (const float*)d_in[1];
    const float* bqkv  = (const float*)d_in[2];
    const float* Wproj = (const float*)d_in[3];
    const float* bproj = (const float*)d_in[4];
    float* out = (float*)d_out;

    __nv_bfloat16 *qh, *ql, *kh, *kl, *vh, *vl, *xh, *xl, *ah, *al;
    __nv_bfloat16 *wqh, *wql, *wph, *wpl;
    cudaGetSymbolAddress((void**)&qh, g_qh);   cudaGetSymbolAddress((void**)&ql, g_ql);
    cudaGetSymbolAddress((void**)&kh, g_kh);   cudaGetSymbolAddress((void**)&kl, g_kl);
    cudaGetSymbolAddress((void**)&vh, g_vh);   cudaGetSymbolAddress((void**)&vl, g_vl);
    cudaGetSymbolAddress((void**)&xh, g_xh);   cudaGetSymbolAddress((void**)&xl, g_xl);
    cudaGetSymbolAddress((void**)&ah, g_ah);   cudaGetSymbolAddress((void**)&al, g_al);
    cudaGetSymbolAddress((void**)&wqh, g_wqh); cudaGetSymbolAddress((void**)&wql, g_wql);
    cudaGetSymbolAddress((void**)&wph, g_wph); cudaGetSymbolAddress((void**)&wpl, g_wpl);

    cudaFuncSetAttribute(gemm_mma_kernel<0>,
                         cudaFuncAttributeMaxDynamicSharedMemorySize, GSMEM);
    cudaFuncSetAttribute(gemm_mma_kernel<1>,
                         cudaFuncAttributeMaxDynamicSharedMemorySize, GSMEM);
    cudaFuncSetAttribute(flash_attn_mma,
                         cudaFuncAttributeMaxDynamicSharedMemorySize, FA_SMEM);

    split_kernel<<<(M_ROWS * C_DIM / 4 + 255) / 256, 256>>>(x, xh, xl, M_ROWS * C_DIM / 4);
    transpose_split_kernel<<<dim3(C3 / 32, C_DIM / 32), dim3(32, 8)>>>(Wqkv, wqh, wql, C_DIM, C3);
    transpose_split_kernel<<<dim3(C_DIM / 32, C_DIM / 32), dim3(32, 8)>>>(Wproj, wph, wpl, C_DIM, C_DIM);

    // 1) qkv projection -> bf16 hi/lo q/k/v buffers directly
    gemm_mma_kernel<1><<<dim3(C3 / 128, M_ROWS / 128), 128, GSMEM>>>(
        xh, xl, wqh, wql, bqkv, nullptr, M_ROWS, C3, C_DIM,
        qh, ql, kh, kl, vh, vl);

    // 2) attention -> bf16 hi/lo
    flash_attn_mma<<<dim3(T_SZ / 128, B_SZ * NH), 256, FA_SMEM>>>(
        qh, ql, kh, kl, vh, vl, ah, al);

    // 3) out = attn @ Wproj + bproj (fp32 out)
    gemm_mma_kernel<0><<<dim3(C_DIM / 128, M_ROWS / 128), 128, GSMEM>>>(
        ah, al, wph, wpl, bproj, out, M_ROWS, C_DIM, C_DIM,
        nullptr, nullptr, nullptr, nullptr, nullptr, nullptr);
}